// round 17
// baseline (speedup 1.0000x reference)
#include <cuda_runtime.h>
#include <cuda_bf16.h>
#include <math.h>
#include <stdint.h>

// ---------------------------------------------------------------------------
// DAttention forward. B=4, C=512, H=W=32 (HW=1024), HEADS=8, HC=64,
// G=4, GC=128, n=1024. Projection GEMMs via bf16 m16n8k16 3-split with
// ldmatrix fragment loads. Attention: flash-style fused kernel.
// ---------------------------------------------------------------------------

#define Bc     4
#define Cc     512
#define Hh     32
#define Ww     32
#define HW     1024
#define HEADS  8
#define HC     64
#define Gg     4
#define GC     128
#define BG     16
#define NH     32
#define NPTS   1024
#define SCALE  0.125f
#define RPE_W  63
#define WP_ELEMS (512*256)

// ------------------------------ scratch ------------------------------------
__device__ float g_q     [Bc*Cc*HW];
__device__ float g_o1    [BG*GC*HW];
__device__ float g_pos   [BG*NPTS*2];
__device__ float g_xs    [Bc*Cc*NPTS];
__device__ float g_k     [Bc*Cc*NPTS];
__device__ float g_v     [Bc*Cc*NPTS];
__device__ float g_outbuf[Bc*Cc*HW];
__device__ uint32_t g_wph[4*WP_ELEMS];
__device__ uint32_t g_wpl[4*WP_ELEMS];

// --------------------------- bf16 helpers -----------------------------------
__device__ __forceinline__ void split_bf2(float v0, float v1, uint32_t& hi, uint32_t& lo) {
    __nv_bfloat16 h0 = __float2bfloat16_rn(v0);
    __nv_bfloat16 h1 = __float2bfloat16_rn(v1);
    __nv_bfloat16 l0 = __float2bfloat16_rn(v0 - __bfloat162float(h0));
    __nv_bfloat16 l1 = __float2bfloat16_rn(v1 - __bfloat162float(h1));
    hi = ((uint32_t)__bfloat16_as_ushort(h1) << 16) | (uint32_t)__bfloat16_as_ushort(h0);
    lo = ((uint32_t)__bfloat16_as_ushort(l1) << 16) | (uint32_t)__bfloat16_as_ushort(l0);
}
__device__ __forceinline__ void mma16(float* d, const uint32_t* a, const uint32_t* b) {
    asm volatile(
        "mma.sync.aligned.m16n8k16.row.col.f32.bf16.bf16.f32 "
        "{%0,%1,%2,%3},{%4,%5,%6,%7},{%8,%9},{%0,%1,%2,%3};"
        : "+f"(d[0]), "+f"(d[1]), "+f"(d[2]), "+f"(d[3])
        : "r"(a[0]), "r"(a[1]), "r"(a[2]), "r"(a[3]), "r"(b[0]), "r"(b[1]));
}
__device__ __forceinline__ void ldm4(uint32_t* r, uint32_t addr) {
    asm volatile("ldmatrix.sync.aligned.m8n8.x4.shared.b16 {%0,%1,%2,%3}, [%4];"
                 : "=r"(r[0]), "=r"(r[1]), "=r"(r[2]), "=r"(r[3]) : "r"(addr));
}
__device__ __forceinline__ uint32_t smem_u32(const void* p) {
    return (uint32_t)__cvta_generic_to_shared(p);
}

// ---------------- weight pre-split: fp32 [512][512] -> bf16 pairs ------------
__global__ void split_w2(const float* __restrict__ a, const float* __restrict__ c,
                         uint32_t* __restrict__ ha, uint32_t* __restrict__ la,
                         uint32_t* __restrict__ hc, uint32_t* __restrict__ lc) {
    int i = blockIdx.x * 256 + threadIdx.x;
    float2 v = *(const float2*)(a + 2 * (size_t)i);
    split_bf2(v.x, v.y, ha[i], la[i]);
    if (c) {
        float2 w = *(const float2*)(c + 2 * (size_t)i);
        split_bf2(w.x, w.y, hc[i], lc[i]);
    }
}

// ---------------- projection GEMM (bf16x3, ldmatrix frags) ------------------
// C[z] (512 x Nn) = W @ B[z] + bias. A smem [m][kp] s12; B smem [n][kp] s12.
__global__ __launch_bounds__(256) void proj_gemm_bf(
        const uint32_t* __restrict__ Aph, const uint32_t* __restrict__ Apl,
        const float* __restrict__ Bm, const float* __restrict__ bias,
        float* __restrict__ Cm, int Nn) {
    const int Kk = 512, KP = 256;
    __shared__ uint32_t Ah[128 * 12], Al[128 * 12];   // [m][kp 0..7], stride 12
    __shared__ uint32_t Bh[64 * 12],  Bl[64 * 12];    // [n][kp 0..7], stride 12
    const float* B = Bm + (size_t)blockIdx.z * Kk * Nn;
    float*       C = Cm + (size_t)blockIdx.z * 512 * Nn;
    int m0 = blockIdx.y * 128, n0 = blockIdx.x * 64;
    int tid = threadIdx.x, warp = tid >> 5, lane = tid & 31;
    int wm = (warp & 3) * 32, wn = (warp >> 2) * 32;
    int g = lane >> 2, tg = lane & 3;

    // ldmatrix lane addresses (k-invariant: smem holds only current k-tile)
    int aRow = wm + (lane & 7) + ((lane >> 3) & 1) * 8;
    int aCol = ((lane >> 4) & 1) * 4;
    uint32_t aAh0 = smem_u32(&Ah[aRow * 12 + aCol]);
    uint32_t aAl0 = smem_u32(&Al[aRow * 12 + aCol]);
    const uint32_t MT_OFF = 16 * 12 * 4;   // +16 m-rows
    int bRow = wn + (lane & 7) + ((lane >> 4) & 1) * 8;
    int bCol = ((lane >> 3) & 1) * 4;
    uint32_t bBh0 = smem_u32(&Bh[bRow * 12 + bCol]);
    uint32_t bBl0 = smem_u32(&Bl[bRow * 12 + bCol]);
    const uint32_t NTP_OFF = 16 * 12 * 4;  // +16 n-rows

    float acc[2][4][4] = {};
    for (int k0 = 0; k0 < Kk; k0 += 16) {
        int kp0 = k0 >> 1;
        {
            int r = tid >> 2, kc = (tid & 3) * 2;
            #pragma unroll
            for (int i = 0; i < 2; i++) {
                int m = r + i * 64;
                uint2 vh = *(const uint2*)(Aph + (size_t)(m0 + m) * KP + kp0 + kc);
                uint2 vl = *(const uint2*)(Apl + (size_t)(m0 + m) * KP + kp0 + kc);
                Ah[m*12+kc] = vh.x; Ah[m*12+kc+1] = vh.y;
                Al[m*12+kc] = vl.x; Al[m*12+kc+1] = vl.y;
            }
            int kp = tid >> 6, n = tid & 63;
            #pragma unroll
            for (int i = 0; i < 2; i++) {
                int kpp = kp + i * 4;
                float v0 = B[(size_t)(k0 + 2*kpp    ) * Nn + n0 + n];
                float v1 = B[(size_t)(k0 + 2*kpp + 1) * Nn + n0 + n];
                split_bf2(v0, v1, Bh[n*12 + kpp], Bl[n*12 + kpp]);
            }
        }
        __syncthreads();
        {
            uint32_t aH[2][4], aL[2][4], bH[4][2], bL[4][2];
            ldm4(aH[0], aAh0);           ldm4(aH[1], aAh0 + MT_OFF);
            ldm4(aL[0], aAl0);           ldm4(aL[1], aAl0 + MT_OFF);
            uint32_t tmp[4];
            ldm4(tmp, bBh0);
            bH[0][0]=tmp[0]; bH[0][1]=tmp[1]; bH[1][0]=tmp[2]; bH[1][1]=tmp[3];
            ldm4(tmp, bBh0 + NTP_OFF);
            bH[2][0]=tmp[0]; bH[2][1]=tmp[1]; bH[3][0]=tmp[2]; bH[3][1]=tmp[3];
            ldm4(tmp, bBl0);
            bL[0][0]=tmp[0]; bL[0][1]=tmp[1]; bL[1][0]=tmp[2]; bL[1][1]=tmp[3];
            ldm4(tmp, bBl0 + NTP_OFF);
            bL[2][0]=tmp[0]; bL[2][1]=tmp[1]; bL[3][0]=tmp[2]; bL[3][1]=tmp[3];
            #pragma unroll
            for (int mt = 0; mt < 2; mt++)
                #pragma unroll
                for (int nt = 0; nt < 4; nt++) {
                    mma16(acc[mt][nt], aH[mt], bH[nt]);
                    mma16(acc[mt][nt], aH[mt], bL[nt]);
                    mma16(acc[mt][nt], aL[mt], bH[nt]);
                }
        }
        __syncthreads();
    }
    #pragma unroll
    for (int mt = 0; mt < 2; mt++)
        #pragma unroll
        for (int i = 0; i < 2; i++) {
            int m = m0 + wm + mt * 16 + g + i * 8;
            float bv = bias ? bias[m] : 0.f;
            #pragma unroll
            for (int nt = 0; nt < 4; nt++) {
                float2 v2 = make_float2(acc[mt][nt][2*i] + bv, acc[mt][nt][2*i+1] + bv);
                *(float2*)(C + (size_t)m * Nn + n0 + wn + nt * 8 + 2 * tg) = v2;
            }
        }
}

// ------------- flash attention: QK + bias + softmax + PV fused --------------
#define SM_QH 0
#define SM_QL 2304
#define SM_KH 4608
#define SM_KL 6912
#define SM_VH 9216
#define SM_VL 11520
#define SM_TAB 13824
#define SM_POS 17793
#define SM_WORDS 19841

extern __shared__ uint32_t dsm[];
__global__ __launch_bounds__(128) void flash_attn(const float* __restrict__ rpe) {
    int h = blockIdx.y, b = h >> 3, hh = h & 7;
    int bg = b * Gg + (hh >> 1);
    int m0 = blockIdx.x * 64;
    uint32_t* Qh = dsm + SM_QH;  uint32_t* Ql = dsm + SM_QL;
    uint32_t* Kh = dsm + SM_KH;  uint32_t* Kl = dsm + SM_KL;
    uint32_t* Vh = dsm + SM_VH;  uint32_t* Vl = dsm + SM_VL;
    float* tab  = (float*)(dsm + SM_TAB);
    float* spos = (float*)(dsm + SM_POS);
    const float* Qg = g_q + (size_t)(b * Cc + hh * HC) * HW;
    const float* Kg = g_k + (size_t)(b * Cc + hh * HC) * NPTS;
    const float* Vg = g_v + (size_t)(b * Cc + hh * HC) * NPTS;
    float*       Og = g_outbuf + (size_t)(b * Cc + hh * HC) * HW;
    int tid = threadIdx.x, warp = tid >> 5, lane = tid & 31;
    int g = lane >> 2, tg = lane & 3;
    int mr = warp * 16;

    for (int i = tid; i < RPE_W * RPE_W; i += 128) tab[i] = rpe[(size_t)hh * RPE_W * RPE_W + i];
    for (int i = tid; i < NPTS * 2; i += 128)      spos[i] = g_pos[(size_t)bg * NPTS * 2 + i];
    {
        int kp = tid >> 2, mb = (tid & 3) * 16;
        const float* re = Qg + (size_t)(2 * kp) * HW + m0 + mb;
        const float* ro = re + HW;
        #pragma unroll
        for (int j = 0; j < 16; j += 2) {
            float2 e = *(const float2*)(re + j);
            float2 o = *(const float2*)(ro + j);
            split_bf2(e.x, o.x, Qh[kp*72 + mb + j],     Ql[kp*72 + mb + j]);
            split_bf2(e.y, o.y, Qh[kp*72 + mb + j + 1], Ql[kp*72 + mb + j + 1]);
        }
    }
    __syncthreads();

    int r0 = m0 + mr + g, r1 = r0 + 8;
    float qy0 = (float)(r0 >> 5) * (2.f/31.f) - 1.f, qx0 = (float)(r0 & 31) * (2.f/31.f) - 1.f;
    float qy1 = (float)(r1 >> 5) * (2.f/31.f) - 1.f, qx1 = (float)(r1 & 31) * (2.f/31.f) - 1.f;

    float oacc[8][4] = {};
    float msf0 = -1e30f, msf1 = -1e30f, l0 = 0.f, l1 = 0.f;

    for (int ch = 0; ch < 16; ch++) {
        int n0c = ch * 64;
        {
            int kp = tid >> 2, nb = (tid & 3) * 16;
            const float* re = Kg + (size_t)(2 * kp) * NPTS + n0c + nb;
            const float* ro = re + NPTS;
            #pragma unroll
            for (int j = 0; j < 16; j += 2) {
                float2 e = *(const float2*)(re + j);
                float2 o = *(const float2*)(ro + j);
                split_bf2(e.x, o.x, Kh[kp*72 + nb + j],     Kl[kp*72 + nb + j]);
                split_bf2(e.y, o.y, Kh[kp*72 + nb + j + 1], Kl[kp*72 + nb + j + 1]);
            }
            int c = tid >> 1, half = tid & 1;
            const float* rv = Vg + (size_t)c * NPTS + n0c + 32 * half;
            #pragma unroll
            for (int t2 = 0; t2 < 32; t2 += 4) {
                float4 v = *(const float4*)(rv + t2);
                int kp2 = 16 * half + (t2 >> 1);
                split_bf2(v.x, v.y, Vh[c*36 + kp2],     Vl[c*36 + kp2]);
                split_bf2(v.z, v.w, Vh[c*36 + kp2 + 1], Vl[c*36 + kp2 + 1]);
            }
        }
        __syncthreads();

        float sacc[8][4] = {};
        #pragma unroll
        for (int ks = 0; ks < 4; ks++) {
            uint32_t qa[4], ql[4];
            qa[0] = Qh[(8*ks+tg  )*72 + mr+g  ]; ql[0] = Ql[(8*ks+tg  )*72 + mr+g  ];
            qa[1] = Qh[(8*ks+tg  )*72 + mr+g+8]; ql[1] = Ql[(8*ks+tg  )*72 + mr+g+8];
            qa[2] = Qh[(8*ks+tg+4)*72 + mr+g  ]; ql[2] = Ql[(8*ks+tg+4)*72 + mr+g  ];
            qa[3] = Qh[(8*ks+tg+4)*72 + mr+g+8]; ql[3] = Ql[(8*ks+tg+4)*72 + mr+g+8];
            #pragma unroll
            for (int nt = 0; nt < 8; nt++) {
                int nc = nt * 8 + g;
                uint32_t kb[2], kl2[2];
                kb[0]  = Kh[(8*ks+tg  )*72 + nc]; kb[1]  = Kh[(8*ks+tg+4)*72 + nc];
                kl2[0] = Kl[(8*ks+tg  )*72 + nc]; kl2[1] = Kl[(8*ks+tg+4)*72 + nc];
                mma16(sacc[nt], qa, kb);
                mma16(sacc[nt], qa, kl2);
                mma16(sacc[nt], ql, kb);
            }
        }

        float cmax0 = -1e30f, cmax1 = -1e30f;
        #pragma unroll
        for (int nt = 0; nt < 8; nt++) {
            #pragma unroll
            for (int j = 0; j < 4; j++) {
                int n = n0c + nt * 8 + 2 * tg + (j & 1);
                float qy = (j < 2) ? qy0 : qy1, qx = (j < 2) ? qx0 : qx1;
                float py = spos[n * 2], px = spos[n * 2 + 1];
                float dyv = (qy - py) * 0.5f, dxv = (qx - px) * 0.5f;
                float gx = (dxv + 1.f) * 0.5f * (RPE_W - 1);
                float gy = (dyv + 1.f) * 0.5f * (RPE_W - 1);
                float x0f = floorf(gx), y0f = floorf(gy);
                float wx = gx - x0f, wy = gy - y0f;
                int x0 = min(max((int)x0f, 0), RPE_W - 1);
                int x1 = min(max((int)x0f + 1, 0), RPE_W - 1);
                int y0 = min(max((int)y0f, 0), RPE_W - 1);
                int y1 = min(max((int)y0f + 1, 0), RPE_W - 1);
                float bias = tab[y0*RPE_W + x0] * (1.f-wx) * (1.f-wy)
                           + tab[y0*RPE_W + x1] * wx * (1.f-wy)
                           + tab[y1*RPE_W + x0] * (1.f-wx) * wy
                           + tab[y1*RPE_W + x1] * wx * wy;
                float s = sacc[nt][j] * SCALE + bias;
                sacc[nt][j] = s;
                if (j < 2) cmax0 = fmaxf(cmax0, s); else cmax1 = fmaxf(cmax1, s);
            }
        }
        cmax0 = fmaxf(cmax0, __shfl_xor_sync(0xFFFFFFFFu, cmax0, 1));
        cmax0 = fmaxf(cmax0, __shfl_xor_sync(0xFFFFFFFFu, cmax0, 2));
        cmax1 = fmaxf(cmax1, __shfl_xor_sync(0xFFFFFFFFu, cmax1, 1));
        cmax1 = fmaxf(cmax1, __shfl_xor_sync(0xFFFFFFFFu, cmax1, 2));

        float mn0 = fmaxf(msf0, cmax0), mn1 = fmaxf(msf1, cmax1);
        float sc0 = __expf(msf0 - mn0),  sc1 = __expf(msf1 - mn1);
        msf0 = mn0; msf1 = mn1;
        float ps0 = 0.f, ps1 = 0.f;
        #pragma unroll
        for (int nt = 0; nt < 8; nt++) {
            #pragma unroll
            for (int j = 0; j < 4; j++) {
                float p = __expf(sacc[nt][j] - ((j < 2) ? mn0 : mn1));
                sacc[nt][j] = p;
                if (j < 2) ps0 += p; else ps1 += p;
            }
        }
        l0 = l0 * sc0 + ps0;
        l1 = l1 * sc1 + ps1;
        #pragma unroll
        for (int ct = 0; ct < 8; ct++) {
            oacc[ct][0] *= sc0; oacc[ct][1] *= sc0;
            oacc[ct][2] *= sc1; oacc[ct][3] *= sc1;
        }

        #pragma unroll
        for (int j2 = 0; j2 < 4; j2++) {
            uint32_t pa[4], pl[4];
            split_bf2(sacc[2*j2  ][0], sacc[2*j2  ][1], pa[0], pl[0]);
            split_bf2(sacc[2*j2  ][2], sacc[2*j2  ][3], pa[1], pl[1]);
            split_bf2(sacc[2*j2+1][0], sacc[2*j2+1][1], pa[2], pl[2]);
            split_bf2(sacc[2*j2+1][2], sacc[2*j2+1][3], pa[3], pl[3]);
            #pragma unroll
            for (int ct = 0; ct < 8; ct++) {
                int cc = ct * 8 + g;
                uint32_t vb[2], vl2[2];
                vb[0]  = Vh[cc*36 + 8*j2 + tg]; vb[1]  = Vh[cc*36 + 8*j2 + tg + 4];
                vl2[0] = Vl[cc*36 + 8*j2 + tg]; vl2[1] = Vl[cc*36 + 8*j2 + tg + 4];
                mma16(oacc[ct], pa, vb);
                mma16(oacc[ct], pa, vl2);
                mma16(oacc[ct], pl, vb);
            }
        }
        __syncthreads();
    }

    l0 += __shfl_xor_sync(0xFFFFFFFFu, l0, 1);
    l0 += __shfl_xor_sync(0xFFFFFFFFu, l0, 2);
    l1 += __shfl_xor_sync(0xFFFFFFFFu, l1, 1);
    l1 += __shfl_xor_sync(0xFFFFFFFFu, l1, 2);
    float inv0 = 1.f / l0, inv1 = 1.f / l1;
    #pragma unroll
    for (int ct = 0; ct < 8; ct++) {
        int c0 = ct * 8 + 2 * tg;
        Og[(size_t)(c0    ) * HW + r0] = oacc[ct][0] * inv0;
        Og[(size_t)(c0 + 1) * HW + r0] = oacc[ct][1] * inv0;
        Og[(size_t)(c0    ) * HW + r1] = oacc[ct][2] * inv1;
        Og[(size_t)(c0 + 1) * HW + r1] = oacc[ct][3] * inv1;
    }
}

// ------------------------- depthwise 3x3 conv -------------------------------
__global__ void dwconv3x3(const float* __restrict__ w,
                          const float* __restrict__ bias) {
    int bg = blockIdx.z, ch = blockIdx.y;
    int x  = threadIdx.x;
    int y  = blockIdx.x * blockDim.y + threadIdx.y;
    const float* img = g_q + ((size_t)bg * GC + ch) * HW;
    const float* wc  = w + ch * 9;
    float s = bias[ch];
    #pragma unroll
    for (int dy = -1; dy <= 1; dy++) {
        int yy = y + dy;
        if (yy < 0 || yy >= Hh) continue;
        #pragma unroll
        for (int dx = -1; dx <= 1; dx++) {
            int xx = x + dx;
            if (xx < 0 || xx >= Ww) continue;
            s += img[yy * Ww + xx] * wc[(dy + 1) * 3 + (dx + 1)];
        }
    }
    g_o1[((size_t)bg * GC + ch) * HW + y * Ww + x] = s;
}

// -------- LayerNorm + GELU + 1x1-conv-to-2 + ref + clip (fused) -------------
__global__ void ln_gelu_offset(const float* __restrict__ lnw,
                               const float* __restrict__ lnb,
                               const float* __restrict__ pw,
                               float* __restrict__ outPos,
                               float* __restrict__ outRef) {
    int bg = blockIdx.y, y = blockIdx.x;
    int x = threadIdx.x, ty = threadIdx.y;
    __shared__ float s1[4][32], s2[4][32];
    const float* base = g_o1 + (size_t)bg * GC * HW + y * Ww + x;
    float vals[32];
    float sum = 0.f, sq = 0.f;
    #pragma unroll
    for (int i = 0; i < 32; i++) {
        float v = base[(size_t)(ty * 32 + i) * HW];
        vals[i] = v; sum += v; sq += v * v;
    }
    s1[ty][x] = sum; s2[ty][x] = sq;
    __syncthreads();
    if (ty == 0) {
        float S = s1[0][x] + s1[1][x] + s1[2][x] + s1[3][x];
        float Q = s2[0][x] + s2[1][x] + s2[2][x] + s2[3][x];
        float mu = S * (1.f / GC);
        float var = Q * (1.f / GC) - mu * mu;
        s1[0][x] = mu;
        s2[0][x] = rsqrtf(var + 1e-5f);
    }
    __syncthreads();
    float mu = s1[0][x], rs = s2[0][x];
    __syncthreads();
    float d0 = 0.f, d1 = 0.f;
    #pragma unroll
    for (int i = 0; i < 32; i++) {
        int c = ty * 32 + i;
        float v = (vals[i] - mu) * rs * lnw[c] + lnb[c];
        v = 0.5f * v * (1.f + erff(v * 0.70710678118654752f));
        d0 += pw[c] * v;
        d1 += pw[GC + c] * v;
    }
    s1[ty][x] = d0; s2[ty][x] = d1;
    __syncthreads();
    if (ty == 0) {
        float o0 = s1[0][x] + s1[1][x] + s1[2][x] + s1[3][x];
        float o1 = s2[0][x] + s2[1][x] + s2[2][x] + s2[3][x];
        float ry = ((y + 0.5f) / 31.f) * 2.f - 1.f;
        float rx = ((x + 0.5f) / 31.f) * 2.f - 1.f;
        float py = fminf(fmaxf(o0 + ry, -1.f), 1.f);
        float px = fminf(fmaxf(o1 + rx, -1.f), 1.f);
        size_t o = ((size_t)bg * NPTS + y * Ww + x) * 2;
        g_pos[o] = py; g_pos[o + 1] = px;
        if (outPos) { outPos[o] = py; outPos[o + 1] = px; }
        if (outRef) { outRef[o] = ry; outRef[o + 1] = rx; }
    }
}

// ----------------- bilinear sampling of x at pos -> xs ----------------------
__global__ void sample_x(const float* __restrict__ x) {
    int bg  = blockIdx.z;
    int gc0 = blockIdx.y * 16;
    int p   = blockIdx.x * 256 + threadIdx.x;
    size_t po = ((size_t)bg * NPTS + p) * 2;
    float py = g_pos[po], px = g_pos[po + 1];
    float gx = (px + 1.f) * 0.5f * (Ww - 1);
    float gy = (py + 1.f) * 0.5f * (Hh - 1);
    float x0f = floorf(gx), y0f = floorf(gy);
    float wx = gx - x0f, wy = gy - y0f;
    int x0 = min(max((int)x0f, 0), Ww - 1);
    int x1 = min(max((int)x0f + 1, 0), Ww - 1);
    int y0 = min(max((int)y0f, 0), Hh - 1);
    int y1 = min(max((int)y0f + 1, 0), Hh - 1);
    int i00 = y0 * Ww + x0, i01 = y0 * Ww + x1;
    int i10 = y1 * Ww + x0, i11 = y1 * Ww + x1;
    float w00 = (1.f - wx) * (1.f - wy), w01 = wx * (1.f - wy);
    float w10 = (1.f - wx) * wy,         w11 = wx * wy;
    const float* img = x + ((size_t)bg * GC + gc0) * HW;
    float* dst = g_xs + ((size_t)bg * GC + gc0) * NPTS + p;
    #pragma unroll 4
    for (int c = 0; c < 16; c++) {
        const float* im = img + (size_t)c * HW;
        dst[(size_t)c * NPTS] = im[i00] * w00 + im[i01] * w01
                              + im[i10] * w10 + im[i11] * w11;
    }
}

// ---------------------------------------------------------------------------
extern "C" void kernel_launch(void* const* d_in, const int* in_sizes, int n_in,
                              void* d_out, int out_size) {
    const float* x        = (const float*)d_in[0];
    const float* wq       = (const float*)d_in[1];
    const float* bq       = (const float*)d_in[2];
    const float* wk       = (const float*)d_in[3];
    const float* bk       = (const float*)d_in[4];
    const float* wv       = (const float*)d_in[5];
    const float* bv       = (const float*)d_in[6];
    const float* wo       = (const float*)d_in[7];
    const float* bo       = (const float*)d_in[8];
    const float* off_dw_w = (const float*)d_in[9];
    const float* off_dw_b = (const float*)d_in[10];
    const float* ln_w     = (const float*)d_in[11];
    const float* ln_b     = (const float*)d_in[12];
    const float* off_pw_w = (const float*)d_in[13];
    const float* rpe      = (const float*)d_in[14];
    float* out = (float*)d_out;

    float *p_xs, *p_ob;
    uint32_t *p_wph, *p_wpl;
    cudaGetSymbolAddress((void**)&p_xs,  g_xs);
    cudaGetSymbolAddress((void**)&p_ob,  g_outbuf);
    cudaGetSymbolAddress((void**)&p_wph, g_wph);
    cudaGetSymbolAddress((void**)&p_wpl, g_wpl);
    float *p_q, *p_k, *p_v;
    cudaGetSymbolAddress((void**)&p_q, g_q);
    cudaGetSymbolAddress((void**)&p_k, g_k);
    cudaGetSymbolAddress((void**)&p_v, g_v);

    // Idempotent + deterministic; not a stream op, safe under graph capture.
    cudaFuncSetAttribute(flash_attn, cudaFuncAttributeMaxDynamicSharedMemorySize,
                         SM_WORDS * 4);

    const int Y_SIZE = Bc * Cc * HW;
    const int P_SIZE = Bc * Gg * NPTS * 2;
    float* outPos = (out_size >= Y_SIZE + P_SIZE)     ? out + Y_SIZE          : nullptr;
    float* outRef = (out_size >= Y_SIZE + 2 * P_SIZE) ? out + Y_SIZE + P_SIZE : nullptr;

    dim3 gProj(HW / 64, 512 / 128, Bc);

    // 0. pre-split weights
    split_w2<<<512, 256>>>(wq, wk, p_wph, p_wpl,
                           p_wph + WP_ELEMS, p_wpl + WP_ELEMS);
    split_w2<<<512, 256>>>(wv, nullptr, p_wph + 2*WP_ELEMS, p_wpl + 2*WP_ELEMS,
                           nullptr, nullptr);
    split_w2<<<512, 256>>>(wo, nullptr, p_wph + 3*WP_ELEMS, p_wpl + 3*WP_ELEMS,
                           nullptr, nullptr);
    // 1. q = wq x + bq
    proj_gemm_bf<<<gProj, 256>>>(p_wph, p_wpl, x, bq, p_q, HW);
    // 2. offset network
    dwconv3x3<<<dim3(4, GC, BG), dim3(32, 8)>>>(off_dw_w, off_dw_b);
    ln_gelu_offset<<<dim3(Hh, BG), dim3(32, 4)>>>(ln_w, ln_b, off_pw_w, outPos, outRef);
    // 3. deformable sampling
    sample_x<<<dim3(4, 8, BG), 256>>>(x);
    // 4. k, v projections
    proj_gemm_bf<<<gProj, 256>>>(p_wph + WP_ELEMS,   p_wpl + WP_ELEMS,   p_xs, bk, p_k, NPTS);
    proj_gemm_bf<<<gProj, 256>>>(p_wph + 2*WP_ELEMS, p_wpl + 2*WP_ELEMS, p_xs, bv, p_v, NPTS);
    // 5-7. fused attention (QK + rpe bias + softmax + PV)
    flash_attn<<<dim3(HW / 64, NH), 128, SM_WORDS * 4>>>(rpe);
    // 8. y = wo out + bo -> straight into d_out
    proj_gemm_bf<<<gProj, 256>>>(p_wph + 3*WP_ELEMS, p_wpl + 3*WP_ELEMS, p_ob, bo, out, HW);
}